// round 7
// baseline (speedup 1.0000x reference)
#include <cuda_runtime.h>
#include <cuda_bf16.h>
#include <cstdint>

#define B_ 8
#define N_ 1024
#define E_ 1024
#define H_ 16
#define D_ 64

// ---------------------------------------------------------------------------
// Static scratch (allocation-free)
// ---------------------------------------------------------------------------
#define QKV_ELEMS ((size_t)B_ * H_ * N_ * D_)
__device__ __align__(16) __nv_bfloat16 g_qh[QKV_ELEMS];
__device__ __align__(16) __nv_bfloat16 g_ql[QKV_ELEMS];
__device__ __align__(16) __nv_bfloat16 g_kh[QKV_ELEMS];
__device__ __align__(16) __nv_bfloat16 g_kl[QKV_ELEMS];
__device__ __align__(16) __nv_bfloat16 g_vh[QKV_ELEMS];
__device__ __align__(16) __nv_bfloat16 g_vl[QKV_ELEMS];
__device__ __align__(16) __nv_bfloat16 g_ahi[(size_t)8192 * 1024];
__device__ __align__(16) __nv_bfloat16 g_alo[(size_t)8192 * 1024];
__device__ __align__(16) __nv_bfloat16 g_w1hi[(size_t)3072 * 1024];
__device__ __align__(16) __nv_bfloat16 g_w1lo[(size_t)3072 * 1024];
__device__ __align__(16) __nv_bfloat16 g_w2hi[(size_t)1024 * 1024];
__device__ __align__(16) __nv_bfloat16 g_w2lo[(size_t)1024 * 1024];
__device__ __align__(16) __nv_bfloat16 g_aohi[(size_t)8192 * 1024];
__device__ __align__(16) __nv_bfloat16 g_aolo[(size_t)8192 * 1024];

__device__ __forceinline__ uint32_t smem_to_u32(const void* p) {
    uint32_t a;
    asm("{ .reg .u64 t; cvta.to.shared.u64 t, %1; cvt.u32.u64 %0, t; }" : "=r"(a) : "l"(p));
    return a;
}
#define SWZ(o) ((o) ^ (((o) >> 3) & 0x70))

__device__ __forceinline__ void ldsm_x4(uint32_t* d, uint32_t addr) {
    asm volatile("ldmatrix.sync.aligned.m8n8.x4.shared.b16 {%0,%1,%2,%3}, [%4];"
                 : "=r"(d[0]), "=r"(d[1]), "=r"(d[2]), "=r"(d[3]) : "r"(addr));
}
__device__ __forceinline__ void ldsm_x4_t(uint32_t* d, uint32_t addr) {
    asm volatile("ldmatrix.sync.aligned.m8n8.x4.trans.shared.b16 {%0,%1,%2,%3}, [%4];"
                 : "=r"(d[0]), "=r"(d[1]), "=r"(d[2]), "=r"(d[3]) : "r"(addr));
}
__device__ __forceinline__ void mma_bf16(float* c, const uint32_t* a, uint32_t b0, uint32_t b1) {
    asm volatile(
        "mma.sync.aligned.m16n8k16.row.col.f32.bf16.bf16.f32 "
        "{%0,%1,%2,%3}, {%4,%5,%6,%7}, {%8,%9}, {%0,%1,%2,%3};"
        : "+f"(c[0]), "+f"(c[1]), "+f"(c[2]), "+f"(c[3])
        : "r"(a[0]), "r"(a[1]), "r"(a[2]), "r"(a[3]), "r"(b0), "r"(b1));
}
__device__ __forceinline__ void cp_async16(uint32_t sdst, const void* gsrc) {
    asm volatile("cp.async.cg.shared.global [%0], [%1], 16;" :: "r"(sdst), "l"(gsrc));
}
#define CP_COMMIT() asm volatile("cp.async.commit_group;" ::: "memory")
#define CP_WAIT_ALL() asm volatile("cp.async.wait_group 0;" ::: "memory")

// pack two floats into bf16x2 hi/lo error-split pairs
__device__ __forceinline__ void split2(float a, float b, uint32_t& hi2, uint32_t& lo2) {
    __nv_bfloat16 ah = __float2bfloat16_rn(a);
    __nv_bfloat16 bh = __float2bfloat16_rn(b);
    __nv_bfloat16 al = __float2bfloat16_rn(a - __bfloat162float(ah));
    __nv_bfloat16 bl = __float2bfloat16_rn(b - __bfloat162float(bh));
    __nv_bfloat162 h2; h2.x = ah; h2.y = bh;
    __nv_bfloat162 l2; l2.x = al; l2.y = bl;
    hi2 = *reinterpret_cast<uint32_t*>(&h2);
    lo2 = *reinterpret_cast<uint32_t*>(&l2);
}

// ---------------------------------------------------------------------------
// fp32 -> (bf16 hi, bf16 lo) split
// ---------------------------------------------------------------------------
__global__ __launch_bounds__(256) void split_bf16(
    const float* __restrict__ x, __nv_bfloat16* __restrict__ hi,
    __nv_bfloat16* __restrict__ lo, int n4)
{
    int i = blockIdx.x * 256 + threadIdx.x;
    if (i >= n4) return;
    float4 v = ((const float4*)x)[i];
    float vv[4] = {v.x, v.y, v.z, v.w};
    ushort4 h, l;
    unsigned short* hp = &h.x;
    unsigned short* lp = &l.x;
#pragma unroll
    for (int j = 0; j < 4; j++) {
        __nv_bfloat16 bh = __float2bfloat16_rn(vv[j]);
        __nv_bfloat16 bl = __float2bfloat16_rn(vv[j] - __bfloat162float(bh));
        hp[j] = *reinterpret_cast<unsigned short*>(&bh);
        lp[j] = *reinterpret_cast<unsigned short*>(&bl);
    }
    ((ushort4*)hi)[i] = h;
    ((ushort4*)lo)[i] = l;
}

// ---------------------------------------------------------------------------
// HMMA bf16-split GEMM (NT), K=1024, 128x128 tile, 256 threads, BK=64,
// cp.async double buffer. Term-major MMA ordering (same-acc distance 16).
// MODE 0: scatter q/k/v bf16 hi/lo head-major; q scaled 0.125
// MODE 1: C = acc + bias[n] -> fp32 out
// ---------------------------------------------------------------------------
#define STAGE_BYTES 65536
#define GEMM_SMEM (2 * STAGE_BYTES)

template <int MODE>
__global__ __launch_bounds__(256, 1)
void gemm_hmma(const __nv_bfloat16* __restrict__ Ah, const __nv_bfloat16* __restrict__ Al,
               const __nv_bfloat16* __restrict__ Bh, const __nv_bfloat16* __restrict__ Bl,
               const float* __restrict__ bias, float* __restrict__ C, int ldc,
               __nv_bfloat16* __restrict__ OQH, __nv_bfloat16* __restrict__ OQL,
               __nv_bfloat16* __restrict__ OKH, __nv_bfloat16* __restrict__ OKL,
               __nv_bfloat16* __restrict__ OVH, __nv_bfloat16* __restrict__ OVL)
{
    extern __shared__ char smem[];
    const uint32_t sb = smem_to_u32(smem);
    const int tid = threadIdx.x;
    const int wid = tid >> 5, lane = tid & 31;
    const int bm = blockIdx.y * 128, bn = blockIdx.x * 128;
    const int wm = wid >> 1, wn = wid & 1;

    const __nv_bfloat16* tb[4] = {
        Ah + (size_t)bm * 1024, Al + (size_t)bm * 1024,
        Bh + (size_t)bn * 1024, Bl + (size_t)bn * 1024 };

    const int rb = tid >> 3;
    const int cg = tid & 7;
    uint32_t soff[4];
#pragma unroll
    for (int it = 0; it < 4; it++)
        soff[it] = SWZ((uint32_t)((rb + it * 32) * 128 + cg * 16));

    const int q = lane >> 3, l8 = lane & 7;
    const int ar = wm * 32 + (q & 1) * 8 + l8;
    const int ac = (q >> 1) * 16;
    const int br = wn * 64 + (q >> 1) * 8 + l8;
    const int bc = (q & 1) * 16;

    float acc[2][8][4];
#pragma unroll
    for (int mt = 0; mt < 2; mt++)
#pragma unroll
        for (int nt = 0; nt < 8; nt++)
#pragma unroll
            for (int e = 0; e < 4; e++) acc[mt][nt][e] = 0.f;

#define ISSUE(kc_, buf_) do {                                                   \
    const uint32_t stage = sb + (uint32_t)(buf_) * STAGE_BYTES;                 \
    _Pragma("unroll")                                                           \
    for (int t = 0; t < 4; t++) {                                               \
        const __nv_bfloat16* gp = tb[t] + (size_t)(kc_) * 64 + cg * 8;          \
        const uint32_t tbase = stage + (uint32_t)t * 16384u;                    \
        _Pragma("unroll")                                                       \
        for (int it = 0; it < 4; it++)                                          \
            cp_async16(tbase + soff[it], gp + (size_t)(rb + it * 32) * 1024);   \
    }                                                                           \
    CP_COMMIT();                                                                \
} while (0)

    ISSUE(0, 0);

    for (int kc = 0; kc < 16; kc++) {
        const int buf = kc & 1;
        CP_WAIT_ALL();
        __syncthreads();
        if (kc < 15) ISSUE(kc + 1, buf ^ 1);

        const uint32_t stage = sb + (uint32_t)buf * STAGE_BYTES;
        const uint32_t sAh = stage, sAl = stage + 16384u;
        const uint32_t sBh = stage + 32768u, sBl = stage + 49152u;

#pragma unroll
        for (int ks = 0; ks < 4; ks++) {
            uint32_t ah[2][4], al[2][4];
#pragma unroll
            for (int mt = 0; mt < 2; mt++) {
                const uint32_t off = SWZ((uint32_t)((ar + mt * 16) * 128 + ac + ks * 32));
                ldsm_x4(ah[mt], sAh + off);
                ldsm_x4(al[mt], sAl + off);
            }
            uint32_t bhf[4][4], blf[4][4];
#pragma unroll
            for (int jp = 0; jp < 4; jp++) {
                const uint32_t off = SWZ((uint32_t)((br + jp * 16) * 128 + bc + ks * 32));
                ldsm_x4(bhf[jp], sBh + off);
                ldsm_x4(blf[jp], sBl + off);
            }
            // term hh (16 independent accs)
#pragma unroll
            for (int mt = 0; mt < 2; mt++)
#pragma unroll
                for (int jp = 0; jp < 4; jp++) {
                    mma_bf16(acc[mt][2 * jp + 0], ah[mt], bhf[jp][0], bhf[jp][1]);
                    mma_bf16(acc[mt][2 * jp + 1], ah[mt], bhf[jp][2], bhf[jp][3]);
                }
            // term hl
#pragma unroll
            for (int mt = 0; mt < 2; mt++)
#pragma unroll
                for (int jp = 0; jp < 4; jp++) {
                    mma_bf16(acc[mt][2 * jp + 0], ah[mt], blf[jp][0], blf[jp][1]);
                    mma_bf16(acc[mt][2 * jp + 1], ah[mt], blf[jp][2], blf[jp][3]);
                }
            // term lh
#pragma unroll
            for (int mt = 0; mt < 2; mt++)
#pragma unroll
                for (int jp = 0; jp < 4; jp++) {
                    mma_bf16(acc[mt][2 * jp + 0], al[mt], bhf[jp][0], bhf[jp][1]);
                    mma_bf16(acc[mt][2 * jp + 1], al[mt], bhf[jp][2], bhf[jp][3]);
                }
        }
    }
#undef ISSUE

    const int g = lane >> 2, tg = lane & 3;
    if (MODE == 0) {
        const int which = bn >> 10;
        __nv_bfloat16* dh = (which == 0) ? OQH : ((which == 1) ? OKH : OVH);
        __nv_bfloat16* dl = (which == 0) ? OQL : ((which == 1) ? OKL : OVL);
        const float sc = (which == 0) ? 0.125f : 1.0f;
#pragma unroll
        for (int mt = 0; mt < 2; mt++) {
            const int row0 = bm + wm * 32 + mt * 16 + g;
            const int bidx = row0 >> 10, tt = row0 & 1023;
#pragma unroll
            for (int nt = 0; nt < 8; nt++) {
                const int col = bn + wn * 64 + nt * 8 + tg * 2;
                const int e = col & 1023, hh = e >> 6, dd = e & 63;
                const size_t i0 = (((size_t)bidx * 16 + hh) * 1024 + tt) * 64 + dd;
                uint32_t h2, l2;
                split2(acc[mt][nt][0] * sc, acc[mt][nt][1] * sc, h2, l2);
                *(uint32_t*)(dh + i0) = h2;
                *(uint32_t*)(dl + i0) = l2;
                split2(acc[mt][nt][2] * sc, acc[mt][nt][3] * sc, h2, l2);
                *(uint32_t*)(dh + i0 + 8 * 64) = h2;
                *(uint32_t*)(dl + i0 + 8 * 64) = l2;
            }
        }
    } else {
#pragma unroll
        for (int mt = 0; mt < 2; mt++) {
            const int row0 = bm + wm * 32 + mt * 16 + g;
#pragma unroll
            for (int nt = 0; nt < 8; nt++) {
                const int col = bn + wn * 64 + nt * 8 + tg * 2;
                const float b0v = bias[col], b1v = bias[col + 1];
                *(float2*)(C + (size_t)row0 * ldc + col) =
                    make_float2(acc[mt][nt][0] + b0v, acc[mt][nt][1] + b1v);
                *(float2*)(C + (size_t)(row0 + 8) * ldc + col) =
                    make_float2(acc[mt][nt][2] + b0v, acc[mt][nt][3] + b1v);
            }
        }
    }
}

// ---------------------------------------------------------------------------
// Tensor-core flash attention, term-major MMA ordering.
// ---------------------------------------------------------------------------
#define AT_QOFF 4096u
#define AT_KVOFF 36864u
#define AT_SMEM (4096 + 32768 + 65536)

__global__ __launch_bounds__(256, 1) void attn_tc(
    const __nv_bfloat16* __restrict__ qh_, const __nv_bfloat16* __restrict__ ql_,
    const __nv_bfloat16* __restrict__ kh_, const __nv_bfloat16* __restrict__ kl_,
    const __nv_bfloat16* __restrict__ vh_, const __nv_bfloat16* __restrict__ vl_,
    const float* __restrict__ biases,
    __nv_bfloat16* __restrict__ aohi, __nv_bfloat16* __restrict__ aolo)
{
    extern __shared__ char smem[];
    const uint32_t sb = smem_to_u32(smem);
    const int tid = threadIdx.x, wid = tid >> 5, lane = tid & 31;
    const int g = lane >> 2, tg = lane & 3, qq = lane >> 3, l8 = lane & 7;
    const int qi = blockIdx.x, bh = blockIdx.y;
    const int b = bh >> 4, h = bh & 15;
    const int m0 = wid * 16;
    const size_t hb = (size_t)bh << 16;

    float* bias_s = (float*)smem;
    for (int i = tid; i < 1024; i += 256) bias_s[i] = biases[h * 1024 + i];

    {
        const __nv_bfloat16* srcs[2] = { qh_ + hb + (size_t)(qi * 128) * 64,
                                         ql_ + hb + (size_t)(qi * 128) * 64 };
#pragma unroll
        for (int t = 0; t < 2; t++)
#pragma unroll
            for (int i2 = 0; i2 < 4; i2++) {
                const int idx = tid + 256 * i2;
                const int r = idx >> 3, c = idx & 7;
                cp_async16(sb + AT_QOFF + t * 16384u + SWZ((uint32_t)(r * 128 + c * 16)),
                           srcs[t] + (size_t)r * 64 + c * 8);
            }
        CP_COMMIT();
    }

    const __nv_bfloat16* kvp[4] = { kh_ + hb, kl_ + hb, vh_ + hb, vl_ + hb };

#define ISSUE_KV(kt_, buf_) do {                                                  \
    const uint32_t st = sb + AT_KVOFF + (uint32_t)(buf_) * 32768u;                \
    _Pragma("unroll")                                                             \
    for (int t = 0; t < 4; t++) {                                                 \
        const __nv_bfloat16* gp = kvp[t] + (size_t)((kt_) * 64) * 64;             \
        _Pragma("unroll")                                                         \
        for (int i2 = 0; i2 < 2; i2++) {                                          \
            const int idx = tid + 256 * i2;                                       \
            const int r = idx >> 3, c = idx & 7;                                  \
            cp_async16(st + t * 8192u + SWZ((uint32_t)(r * 128 + c * 16)),        \
                       gp + (size_t)r * 64 + c * 8);                              \
        }                                                                         \
    }                                                                             \
    CP_COMMIT();                                                                  \
} while (0)

    ISSUE_KV(0, 0);
    CP_WAIT_ALL();
    __syncthreads();

    uint32_t qfh[4][4], qfl[4][4];
#pragma unroll
    for (int ks = 0; ks < 4; ks++) {
        const uint32_t off =
            SWZ((uint32_t)((m0 + (qq & 1) * 8 + l8) * 128 + (qq >> 1) * 16 + ks * 32));
        ldsm_x4(qfh[ks], sb + AT_QOFF + off);
        ldsm_x4(qfl[ks], sb + AT_QOFF + 16384u + off);
    }

    float O[8][4];
#pragma unroll
    for (int dt = 0; dt < 8; dt++)
#pragma unroll
        for (int e = 0; e < 4; e++) O[dt][e] = 0.f;
    float mr0 = -1e30f, mr1 = -1e30f, lr0 = 0.f, lr1 = 0.f;

    const int i0 = qi * 128 + m0 + g;
    const int ir0 = i0 >> 5, ic0 = i0 & 31;
    const int ir1 = (i0 + 8) >> 5, ic1 = (i0 + 8) & 31;

    for (int kt = 0; kt < 16; kt++) {
        if (kt > 0) { CP_WAIT_ALL(); __syncthreads(); }
        if (kt < 15) ISSUE_KV(kt + 1, (kt + 1) & 1);
        const uint32_t kb = sb + AT_KVOFF + (uint32_t)(kt & 1) * 32768u;

        float s[8][4];
#pragma unroll
        for (int t = 0; t < 8; t++)
#pragma unroll
            for (int e = 0; e < 4; e++) s[t][e] = 0.f;

        // ---- S = Q K^T, term-major per ks (same-acc distance 8) ----
#pragma unroll
        for (int ks = 0; ks < 4; ks++) {
            uint32_t khf[4][4], klf[4][4];
#pragma unroll
            for (int jp = 0; jp < 4; jp++) {
                const uint32_t off = SWZ((uint32_t)(
                    ((qq >> 1) * 8 + l8 + jp * 16) * 128 + (qq & 1) * 16 + ks * 32));
                ldsm_x4(khf[jp], kb + off);
                ldsm_x4(klf[jp], kb + 8192u + off);
            }
#pragma unroll
            for (int jp = 0; jp < 4; jp++) {
                mma_bf16(s[2 * jp + 0], qfh[ks], khf[jp][0], khf[jp][1]);
                mma_bf16(s[2 * jp + 1], qfh[ks], khf[jp][2], khf[jp][3]);
            }
#pragma unroll
            for (int jp = 0; jp < 4; jp++) {
                mma_bf16(s[2 * jp + 0], qfh[ks], klf[jp][0], klf[jp][1]);
                mma_bf16(s[2 * jp + 1], qfh[ks], klf[jp][2], klf[jp][3]);
            }
#pragma unroll
            for (int jp = 0; jp < 4; jp++) {
                mma_bf16(s[2 * jp + 0], qfl[ks], khf[jp][0], khf[jp][1]);
                mma_bf16(s[2 * jp + 1], qfl[ks], khf[jp][2], khf[jp][3]);
            }
        }

#pragma unroll
        for (int t = 0; t < 8; t++) {
            const int j0 = kt * 64 + t * 8 + tg * 2;
            const int jr0 = j0 >> 5, jc0 = j0 & 31;
            const int jr1 = (j0 + 1) >> 5, jc1 = (j0 + 1) & 31;
            s[t][0] += bias_s[abs(ir0 - jr0) * 32 + abs(ic0 - jc0)];
            s[t][1] += bias_s[abs(ir0 - jr1) * 32 + abs(ic0 - jc1)];
            s[t][2] += bias_s[abs(ir1 - jr0) * 32 + abs(ic1 - jc0)];
            s[t][3] += bias_s[abs(ir1 - jr1) * 32 + abs(ic1 - jc1)];
        }

        float mx0 = -1e30f, mx1 = -1e30f;
#pragma unroll
        for (int t = 0; t < 8; t++) {
            mx0 = fmaxf(mx0, fmaxf(s[t][0], s[t][1]));
            mx1 = fmaxf(mx1, fmaxf(s[t][2], s[t][3]));
        }
        mx0 = fmaxf(mx0, __shfl_xor_sync(0xffffffffu, mx0, 1));
        mx0 = fmaxf(mx0, __shfl_xor_sync(0xffffffffu, mx0, 2));
        mx1 = fmaxf(mx1, __shfl_xor_sync(0xffffffffu, mx1, 1));
        mx1 = fmaxf(mx1, __shfl_xor_sync(0xffffffffu, mx1, 2));
        const float mn0 = fmaxf(mr0, mx0), mn1 = fmaxf(mr1, mx1);
        const float a0 = __expf(mr0 - mn0), a1 = __expf(mr1 - mn1);
        mr0 = mn0; mr1 = mn1;
        float sum0 = 0.f, sum1 = 0.f;
#pragma unroll
        for (int t = 0; t < 8; t++) {
            s[t][0] = __expf(s[t][0] - mn0); sum0 += s[t][0];
            s[t][1] = __expf(s[t][1] - mn0); sum0 += s[t][1];
            s[t][2] = __expf(s[t][2] - mn1); sum1 += s[t][2];
            s[t][3] = __expf(s[t][3] - mn1); sum1 += s[t][3];
        }
        sum0 += __shfl_xor_sync(0xffffffffu, sum0, 1);
        sum0 += __shfl_xor_sync(0xffffffffu, sum0, 2);
        sum1 += __shfl_xor_sync(0xffffffffu, sum1, 1);
        sum1 += __shfl_xor_sync(0xffffffffu, sum1, 2);
        lr0 = lr0 * a0 + sum0;
        lr1 = lr1 * a1 + sum1;
#pragma unroll
        for (int dt = 0; dt < 8; dt++) {
            O[dt][0] *= a0; O[dt][1] *= a0;
            O[dt][2] *= a1; O[dt][3] *= a1;
        }

        // ---- O += P V, term-major per js (same-acc distance 8) ----
#pragma unroll
        for (int js = 0; js < 4; js++) {
            uint32_t aph[4], apl[4];
            split2(s[2 * js][0],     s[2 * js][1],     aph[0], apl[0]);
            split2(s[2 * js][2],     s[2 * js][3],     aph[1], apl[1]);
            split2(s[2 * js + 1][0], s[2 * js + 1][1], aph[2], apl[2]);
            split2(s[2 * js + 1][2], s[2 * js + 1][3], aph[3], apl[3]);
            uint32_t vhf[4][4], vlf[4][4];
#pragma unroll
            for (int dp = 0; dp < 4; dp++) {
                const uint32_t off = SWZ((uint32_t)(
                    (js * 16 + (qq & 1) * 8 + l8) * 128 + dp * 32 + (qq >> 1) * 16));
                ldsm_x4_t(vhf[dp], kb + 16384u + off);
                ldsm_x4_t(vlf[dp], kb + 24576u + off);
            }
#pragma unroll
            for (int dp = 0; dp < 4; dp++) {
                mma_bf16(O[2 * dp + 0], aph, vhf[dp][0], vhf[dp][1]);
                mma_bf16(O[2 * dp + 1], aph, vhf[dp][2], vhf[dp][3]);
            }
#pragma unroll
            for (int dp = 0; dp < 4; dp++) {
                mma_bf16(O[2 * dp + 0], aph, vlf[dp][0], vlf[dp][1]);
                mma_bf16(O[2 * dp + 1], aph, vlf[dp][2], vlf[dp][3]);
            }
#pragma unroll
            for (int dp = 0; dp < 4; dp++) {
                mma_bf16(O[2 * dp + 0], apl, vhf[dp][0], vhf[dp][1]);
                mma_bf16(O[2 * dp + 1], apl, vhf[dp][2], vhf[dp][3]);
            }
        }
    }
#undef ISSUE_KV

    const float inv0 = 1.f / lr0, inv1 = 1.f / lr1;
    const int t0 = qi * 128 + m0 + g;
    const size_t base0 = ((size_t)(b * 1024 + t0)) * 1024 + h * 64;
    const size_t base1 = base0 + 8 * 1024;
#pragma unroll
    for (int dt = 0; dt < 8; dt++) {
        const int d0 = dt * 8 + tg * 2;
        uint32_t h2, l2;
        split2(O[dt][0] * inv0, O[dt][1] * inv0, h2, l2);
        *(uint32_t*)(aohi + base0 + d0) = h2;
        *(uint32_t*)(aolo + base0 + d0) = l2;
        split2(O[dt][2] * inv1, O[dt][3] * inv1, h2, l2);
        *(uint32_t*)(aohi + base1 + d0) = h2;
        *(uint32_t*)(aolo + base1 + d0) = l2;
    }
}

// ---------------------------------------------------------------------------
extern "C" void kernel_launch(void* const* d_in, const int* in_sizes, int n_in,
                              void* d_out, int out_size)
{
    (void)in_sizes; (void)n_in; (void)out_size;
    const float* x      = (const float*)d_in[0];
    const float* w_qkv  = (const float*)d_in[1];
    const float* biases = (const float*)d_in[2];
    const float* w_out  = (const float*)d_in[4];
    const float* b_out  = (const float*)d_in[5];
    float* out = (float*)d_out;

    __nv_bfloat16 *qh, *ql, *kh, *kl, *vh, *vl;
    __nv_bfloat16 *ahi, *alo, *w1hi, *w1lo, *w2hi, *w2lo, *aohi, *aolo;
    cudaGetSymbolAddress((void**)&qh, g_qh);
    cudaGetSymbolAddress((void**)&ql, g_ql);
    cudaGetSymbolAddress((void**)&kh, g_kh);
    cudaGetSymbolAddress((void**)&kl, g_kl);
    cudaGetSymbolAddress((void**)&vh, g_vh);
    cudaGetSymbolAddress((void**)&vl, g_vl);
    cudaGetSymbolAddress((void**)&ahi, g_ahi);
    cudaGetSymbolAddress((void**)&alo, g_alo);
    cudaGetSymbolAddress((void**)&w1hi, g_w1hi);
    cudaGetSymbolAddress((void**)&w1lo, g_w1lo);
    cudaGetSymbolAddress((void**)&w2hi, g_w2hi);
    cudaGetSymbolAddress((void**)&w2lo, g_w2lo);
    cudaGetSymbolAddress((void**)&aohi, g_aohi);
    cudaGetSymbolAddress((void**)&aolo, g_aolo);

    cudaFuncSetAttribute(gemm_hmma<0>, cudaFuncAttributeMaxDynamicSharedMemorySize, GEMM_SMEM);
    cudaFuncSetAttribute(gemm_hmma<1>, cudaFuncAttributeMaxDynamicSharedMemorySize, GEMM_SMEM);
    cudaFuncSetAttribute(attn_tc, cudaFuncAttributeMaxDynamicSharedMemorySize, AT_SMEM);

    // 1) bf16 hi/lo splits of inputs
    split_bf16<<<8192, 256>>>(x, ahi, alo, 8192 * 1024 / 4);
    split_bf16<<<3072, 256>>>(w_qkv, w1hi, w1lo, 3072 * 1024 / 4);
    split_bf16<<<1024, 256>>>(w_out, w2hi, w2lo, 1024 * 1024 / 4);

    // 2) QKV projection -> head-major bf16 hi/lo q/k/v (q pre-scaled)
    {
        dim3 grid(3072 / 128, 8192 / 128);
        gemm_hmma<0><<<grid, 256, GEMM_SMEM>>>(ahi, alo, w1hi, w1lo, nullptr, nullptr, 0,
                                               qh, ql, kh, kl, vh, vl);
    }

    // 3) Tensor-core flash attention -> aohi/aolo
    {
        dim3 grid(8, 128);
        attn_tc<<<grid, 256, AT_SMEM>>>(qh, ql, kh, kl, vh, vl, biases, aohi, aolo);
    }

    // 4) Output projection + bias -> fp32 out
    {
        dim3 grid(1024 / 128, 8192 / 128);
        gemm_hmma<1><<<grid, 256, GEMM_SMEM>>>(aohi, aolo, w2hi, w2lo, b_out, out, 1024,
                                               nullptr, nullptr, nullptr, nullptr, nullptr, nullptr);
    }
}

// round 8
// speedup vs baseline: 1.5089x; 1.5089x over previous
#include <cuda_runtime.h>
#include <cuda_bf16.h>
#include <cstdint>

#define B_ 8
#define N_ 1024
#define E_ 1024
#define H_ 16
#define D_ 64

// ---------------------------------------------------------------------------
// Static scratch (allocation-free)
// ---------------------------------------------------------------------------
#define QKV_ELEMS ((size_t)B_ * H_ * N_ * D_)
__device__ __align__(16) __nv_bfloat16 g_qh[QKV_ELEMS];
__device__ __align__(16) __nv_bfloat16 g_ql[QKV_ELEMS];
__device__ __align__(16) __nv_bfloat16 g_kh[QKV_ELEMS];
__device__ __align__(16) __nv_bfloat16 g_kl[QKV_ELEMS];
__device__ __align__(16) __nv_bfloat16 g_vh[QKV_ELEMS];
__device__ __align__(16) __nv_bfloat16 g_vl[QKV_ELEMS];
__device__ __align__(16) __nv_bfloat16 g_ahi[(size_t)8192 * 1024];
__device__ __align__(16) __nv_bfloat16 g_alo[(size_t)8192 * 1024];
__device__ __align__(16) __nv_bfloat16 g_w1hi[(size_t)3072 * 1024];
__device__ __align__(16) __nv_bfloat16 g_w1lo[(size_t)3072 * 1024];
__device__ __align__(16) __nv_bfloat16 g_w2hi[(size_t)1024 * 1024];
__device__ __align__(16) __nv_bfloat16 g_w2lo[(size_t)1024 * 1024];
__device__ __align__(16) __nv_bfloat16 g_aohi[(size_t)8192 * 1024];
__device__ __align__(16) __nv_bfloat16 g_aolo[(size_t)8192 * 1024];

__device__ __forceinline__ uint32_t smem_to_u32(const void* p) {
    uint32_t a;
    asm("{ .reg .u64 t; cvta.to.shared.u64 t, %1; cvt.u32.u64 %0, t; }" : "=r"(a) : "l"(p));
    return a;
}
#define SWZ(o) ((o) ^ (((o) >> 3) & 0x70))

__device__ __forceinline__ void ldsm_x4(uint32_t* d, uint32_t addr) {
    asm volatile("ldmatrix.sync.aligned.m8n8.x4.shared.b16 {%0,%1,%2,%3}, [%4];"
                 : "=r"(d[0]), "=r"(d[1]), "=r"(d[2]), "=r"(d[3]) : "r"(addr));
}
__device__ __forceinline__ void ldsm_x4_t(uint32_t* d, uint32_t addr) {
    asm volatile("ldmatrix.sync.aligned.m8n8.x4.trans.shared.b16 {%0,%1,%2,%3}, [%4];"
                 : "=r"(d[0]), "=r"(d[1]), "=r"(d[2]), "=r"(d[3]) : "r"(addr));
}
__device__ __forceinline__ void mma_bf16(float* c, const uint32_t* a, uint32_t b0, uint32_t b1) {
    asm volatile(
        "mma.sync.aligned.m16n8k16.row.col.f32.bf16.bf16.f32 "
        "{%0,%1,%2,%3}, {%4,%5,%6,%7}, {%8,%9}, {%0,%1,%2,%3};"
        : "+f"(c[0]), "+f"(c[1]), "+f"(c[2]), "+f"(c[3])
        : "r"(a[0]), "r"(a[1]), "r"(a[2]), "r"(a[3]), "r"(b0), "r"(b1));
}
__device__ __forceinline__ void cp_async16(uint32_t sdst, const void* gsrc) {
    asm volatile("cp.async.cg.shared.global [%0], [%1], 16;" :: "r"(sdst), "l"(gsrc));
}
#define CP_COMMIT() asm volatile("cp.async.commit_group;" ::: "memory")
#define CP_WAIT_ALL() asm volatile("cp.async.wait_group 0;" ::: "memory")

// pack two floats into bf16x2 hi/lo error-split pairs
__device__ __forceinline__ void split2(float a, float b, uint32_t& hi2, uint32_t& lo2) {
    __nv_bfloat16 ah = __float2bfloat16_rn(a);
    __nv_bfloat16 bh = __float2bfloat16_rn(b);
    __nv_bfloat16 al = __float2bfloat16_rn(a - __bfloat162float(ah));
    __nv_bfloat16 bl = __float2bfloat16_rn(b - __bfloat162float(bh));
    __nv_bfloat162 h2; h2.x = ah; h2.y = bh;
    __nv_bfloat162 l2; l2.x = al; l2.y = bl;
    hi2 = *reinterpret_cast<uint32_t*>(&h2);
    lo2 = *reinterpret_cast<uint32_t*>(&l2);
}

// ---------------------------------------------------------------------------
// fp32 -> (bf16 hi, bf16 lo) split
// ---------------------------------------------------------------------------
__global__ __launch_bounds__(256) void split_bf16(
    const float* __restrict__ x, __nv_bfloat16* __restrict__ hi,
    __nv_bfloat16* __restrict__ lo, int n4)
{
    int i = blockIdx.x * 256 + threadIdx.x;
    if (i >= n4) return;
    float4 v = ((const float4*)x)[i];
    float vv[4] = {v.x, v.y, v.z, v.w};
    ushort4 h, l;
    unsigned short* hp = &h.x;
    unsigned short* lp = &l.x;
#pragma unroll
    for (int j = 0; j < 4; j++) {
        __nv_bfloat16 bh = __float2bfloat16_rn(vv[j]);
        __nv_bfloat16 bl = __float2bfloat16_rn(vv[j] - __bfloat162float(bh));
        hp[j] = *reinterpret_cast<unsigned short*>(&bh);
        lp[j] = *reinterpret_cast<unsigned short*>(&bl);
    }
    ((ushort4*)hi)[i] = h;
    ((ushort4*)lo)[i] = l;
}

// ---------------------------------------------------------------------------
// HMMA bf16-split GEMM (NT), K=1024, 128x256 CTA tile, 256 threads,
// 8 warps in 2(m) x 4(n), warp tile 64x64 (mt=4, 8 nt). BK=64, cp.async x2.
// Interleaved (R4) MMA ordering. LDSM bytes/MMA reduced 1.5x vs 32x64 tile.
// MODE 0: scatter q/k/v bf16 hi/lo head-major; q scaled 0.125
// MODE 1: C = acc + bias[n] -> fp32 out
// ---------------------------------------------------------------------------
#define STAGE_BYTES 98304u
#define GEMM_SMEM (2 * 98304)

template <int MODE>
__global__ __launch_bounds__(256, 1)
void gemm_hmma(const __nv_bfloat16* __restrict__ Ah, const __nv_bfloat16* __restrict__ Al,
               const __nv_bfloat16* __restrict__ Bh, const __nv_bfloat16* __restrict__ Bl,
               const float* __restrict__ bias, float* __restrict__ C, int ldc,
               __nv_bfloat16* __restrict__ OQH, __nv_bfloat16* __restrict__ OQL,
               __nv_bfloat16* __restrict__ OKH, __nv_bfloat16* __restrict__ OKL,
               __nv_bfloat16* __restrict__ OVH, __nv_bfloat16* __restrict__ OVL)
{
    extern __shared__ char smem[];
    const uint32_t sb = smem_to_u32(smem);
    const int tid = threadIdx.x;
    const int wid = tid >> 5, lane = tid & 31;
    const int bm = blockIdx.y * 128, bn = blockIdx.x * 256;
    const int wm = wid >> 2, wn = wid & 3;   // 2m x 4n warps

    const __nv_bfloat16* tA[2] = { Ah + (size_t)bm * 1024, Al + (size_t)bm * 1024 };
    const __nv_bfloat16* tB[2] = { Bh + (size_t)bn * 1024, Bl + (size_t)bn * 1024 };

    const int q = lane >> 3, l8 = lane & 7;
    const int ar = wm * 64 + (q & 1) * 8 + l8;    // + mt*16
    const int ac = (q >> 1) * 16;                 // + ks*32 (bytes)
    const int br = wn * 64 + (q >> 1) * 8 + l8;   // + jp*16
    const int bc = (q & 1) * 16;                  // + ks*32 (bytes)

    float acc[4][8][4];
#pragma unroll
    for (int mt = 0; mt < 4; mt++)
#pragma unroll
        for (int nt = 0; nt < 8; nt++)
#pragma unroll
            for (int e = 0; e < 4; e++) acc[mt][nt][e] = 0.f;

    // smem layout per stage: Ahi 16K | Alo 16K | Bhi 32K | Blo 32K
#define ISSUE(kc_, buf_) do {                                                     \
    const uint32_t stage = sb + (uint32_t)(buf_) * STAGE_BYTES;                   \
    _Pragma("unroll")                                                             \
    for (int t = 0; t < 2; t++) {                                                 \
        const __nv_bfloat16* gp = tA[t] + (size_t)(kc_) * 64;                     \
        _Pragma("unroll")                                                         \
        for (int i2 = 0; i2 < 4; i2++) {                                          \
            const int idx = tid + 256 * i2;                                       \
            const int r = idx >> 3, c = idx & 7;                                  \
            cp_async16(stage + t * 16384u + SWZ((uint32_t)(r * 128 + c * 16)),    \
                       gp + (size_t)r * 1024 + c * 8);                            \
        }                                                                         \
    }                                                                             \
    _Pragma("unroll")                                                             \
    for (int t = 0; t < 2; t++) {                                                 \
        const __nv_bfloat16* gp = tB[t] + (size_t)(kc_) * 64;                     \
        _Pragma("unroll")                                                         \
        for (int i2 = 0; i2 < 8; i2++) {                                          \
            const int idx = tid + 256 * i2;                                       \
            const int r = idx >> 3, c = idx & 7;                                  \
            cp_async16(stage + 32768u + t * 32768u + SWZ((uint32_t)(r * 128 + c * 16)), \
                       gp + (size_t)r * 1024 + c * 8);                            \
        }                                                                         \
    }                                                                             \
    CP_COMMIT();                                                                  \
} while (0)

    ISSUE(0, 0);

    for (int kc = 0; kc < 16; kc++) {
        const int buf = kc & 1;
        CP_WAIT_ALL();
        __syncthreads();
        if (kc < 15) ISSUE(kc + 1, buf ^ 1);

        const uint32_t stage = sb + (uint32_t)buf * STAGE_BYTES;
        const uint32_t sAh = stage, sAl = stage + 16384u;
        const uint32_t sBh = stage + 32768u, sBl = stage + 65536u;

#pragma unroll
        for (int ks = 0; ks < 4; ks++) {
            uint32_t ah[4][4], al[4][4];
#pragma unroll
            for (int mt = 0; mt < 4; mt++) {
                const uint32_t off = SWZ((uint32_t)((ar + mt * 16) * 128 + ac + ks * 32));
                ldsm_x4(ah[mt], sAh + off);
                ldsm_x4(al[mt], sAl + off);
            }
#pragma unroll
            for (int jp = 0; jp < 4; jp++) {
                uint32_t bh[4], bl[4];
                const uint32_t off = SWZ((uint32_t)((br + jp * 16) * 128 + bc + ks * 32));
                ldsm_x4(bh, sBh + off);
                ldsm_x4(bl, sBl + off);
#pragma unroll
                for (int mt = 0; mt < 4; mt++) {
                    mma_bf16(acc[mt][2 * jp + 0], ah[mt], bh[0], bh[1]);
                    mma_bf16(acc[mt][2 * jp + 1], ah[mt], bh[2], bh[3]);
                    mma_bf16(acc[mt][2 * jp + 0], ah[mt], bl[0], bl[1]);
                    mma_bf16(acc[mt][2 * jp + 1], ah[mt], bl[2], bl[3]);
                    mma_bf16(acc[mt][2 * jp + 0], al[mt], bh[0], bh[1]);
                    mma_bf16(acc[mt][2 * jp + 1], al[mt], bh[2], bh[3]);
                }
            }
        }
    }
#undef ISSUE

    const int g = lane >> 2, tg = lane & 3;
    if (MODE == 0) {
        const int which = bn >> 10;
        __nv_bfloat16* dh = (which == 0) ? OQH : ((which == 1) ? OKH : OVH);
        __nv_bfloat16* dl = (which == 0) ? OQL : ((which == 1) ? OKL : OVL);
        const float sc = (which == 0) ? 0.125f : 1.0f;
#pragma unroll
        for (int mt = 0; mt < 4; mt++) {
            const int row0 = bm + wm * 64 + mt * 16 + g;
            const int bidx = row0 >> 10, tt = row0 & 1023;
#pragma unroll
            for (int nt = 0; nt < 8; nt++) {
                const int col = bn + wn * 64 + nt * 8 + tg * 2;
                const int e = col & 1023, hh = e >> 6, dd = e & 63;
                const size_t i0 = (((size_t)bidx * 16 + hh) * 1024 + tt) * 64 + dd;
                uint32_t h2, l2;
                split2(acc[mt][nt][0] * sc, acc[mt][nt][1] * sc, h2, l2);
                *(uint32_t*)(dh + i0) = h2;
                *(uint32_t*)(dl + i0) = l2;
                split2(acc[mt][nt][2] * sc, acc[mt][nt][3] * sc, h2, l2);
                *(uint32_t*)(dh + i0 + 8 * 64) = h2;
                *(uint32_t*)(dl + i0 + 8 * 64) = l2;
            }
        }
    } else {
#pragma unroll
        for (int mt = 0; mt < 4; mt++) {
            const int row0 = bm + wm * 64 + mt * 16 + g;
#pragma unroll
            for (int nt = 0; nt < 8; nt++) {
                const int col = bn + wn * 64 + nt * 8 + tg * 2;
                const float b0v = bias[col], b1v = bias[col + 1];
                *(float2*)(C + (size_t)row0 * ldc + col) =
                    make_float2(acc[mt][nt][0] + b0v, acc[mt][nt][1] + b1v);
                *(float2*)(C + (size_t)(row0 + 8) * ldc + col) =
                    make_float2(acc[mt][nt][2] + b0v, acc[mt][nt][3] + b1v);
            }
        }
    }
}

// ---------------------------------------------------------------------------
// Tensor-core flash attention (R4/R6 proven version, untouched).
// ---------------------------------------------------------------------------
#define AT_QOFF 4096u
#define AT_KVOFF 36864u
#define AT_SMEM (4096 + 32768 + 65536)

__global__ __launch_bounds__(256, 1) void attn_tc(
    const __nv_bfloat16* __restrict__ qh_, const __nv_bfloat16* __restrict__ ql_,
    const __nv_bfloat16* __restrict__ kh_, const __nv_bfloat16* __restrict__ kl_,
    const __nv_bfloat16* __restrict__ vh_, const __nv_bfloat16* __restrict__ vl_,
    const float* __restrict__ biases,
    __nv_bfloat16* __restrict__ aohi, __nv_bfloat16* __restrict__ aolo)
{
    extern __shared__ char smem[];
    const uint32_t sb = smem_to_u32(smem);
    const int tid = threadIdx.x, wid = tid >> 5, lane = tid & 31;
    const int g = lane >> 2, tg = lane & 3, qq = lane >> 3, l8 = lane & 7;
    const int qi = blockIdx.x, bh = blockIdx.y;
    const int b = bh >> 4, h = bh & 15;
    const int m0 = wid * 16;
    const size_t hb = (size_t)bh << 16;

    float* bias_s = (float*)smem;
    for (int i = tid; i < 1024; i += 256) bias_s[i] = biases[h * 1024 + i];

    {
        const __nv_bfloat16* srcs[2] = { qh_ + hb + (size_t)(qi * 128) * 64,
                                         ql_ + hb + (size_t)(qi * 128) * 64 };
#pragma unroll
        for (int t = 0; t < 2; t++)
#pragma unroll
            for (int i2 = 0; i2 < 4; i2++) {
                const int idx = tid + 256 * i2;
                const int r = idx >> 3, c = idx & 7;
                cp_async16(sb + AT_QOFF + t * 16384u + SWZ((uint32_t)(r * 128 + c * 16)),
                           srcs[t] + (size_t)r * 64 + c * 8);
            }
        CP_COMMIT();
    }

    const __nv_bfloat16* kvp[4] = { kh_ + hb, kl_ + hb, vh_ + hb, vl_ + hb };

#define ISSUE_KV(kt_, buf_) do {                                                  \
    const uint32_t st = sb + AT_KVOFF + (uint32_t)(buf_) * 32768u;                \
    _Pragma("unroll")                                                             \
    for (int t = 0; t < 4; t++) {                                                 \
        const __nv_bfloat16* gp = kvp[t] + (size_t)((kt_) * 64) * 64;             \
        _Pragma("unroll")                                                         \
        for (int i2 = 0; i2 < 2; i2++) {                                          \
            const int idx = tid + 256 * i2;                                       \
            const int r = idx >> 3, c = idx & 7;                                  \
            cp_async16(st + t * 8192u + SWZ((uint32_t)(r * 128 + c * 16)),        \
                       gp + (size_t)r * 64 + c * 8);                              \
        }                                                                         \
    }                                                                             \
    CP_COMMIT();                                                                  \
} while (0)

    ISSUE_KV(0, 0);
    CP_WAIT_ALL();
    __syncthreads();

    uint32_t qfh[4][4], qfl[4][4];
#pragma unroll
    for (int ks = 0; ks < 4; ks++) {
        const uint32_t off =
            SWZ((uint32_t)((m0 + (qq & 1) * 8 + l8) * 128 + (qq >> 1) * 16 + ks * 32));
        ldsm_x4(qfh[ks], sb + AT_QOFF + off);
        ldsm_x4(qfl[ks], sb + AT_QOFF + 16384u + off);
    }

    float O[8][4];
#pragma unroll
    for (int dt = 0; dt < 8; dt++)
#pragma unroll
        for (int e = 0; e < 4; e++) O[dt][e] = 0.f;
    float mr0 = -1e30f, mr1 = -1e30f, lr0 = 0.f, lr1 = 0.f;

    const int i0 = qi * 128 + m0 + g;
    const int ir0 = i0 >> 5, ic0 = i0 & 31;
    const int ir1 = (i0 + 8) >> 5, ic1 = (i0 + 8) & 31;

    for (int kt = 0; kt < 16; kt++) {
        if (kt > 0) { CP_WAIT_ALL(); __syncthreads(); }
        if (kt < 15) ISSUE_KV(kt + 1, (kt + 1) & 1);
        const uint32_t kb = sb + AT_KVOFF + (uint32_t)(kt & 1) * 32768u;

        float s[8][4];
#pragma unroll
        for (int t = 0; t < 8; t++)
#pragma unroll
            for (int e = 0; e < 4; e++) s[t][e] = 0.f;

#pragma unroll
        for (int ks = 0; ks < 4; ks++) {
#pragma unroll
            for (int jp = 0; jp < 4; jp++) {
                uint32_t khf[4], klf[4];
                const uint32_t off = SWZ((uint32_t)(
                    ((qq >> 1) * 8 + l8 + jp * 16) * 128 + (qq & 1) * 16 + ks * 32));
                ldsm_x4(khf, kb + off);
                ldsm_x4(klf, kb + 8192u + off);
                mma_bf16(s[2 * jp + 0], qfh[ks], khf[0], khf[1]);
                mma_bf16(s[2 * jp + 1], qfh[ks], khf[2], khf[3]);
                mma_bf16(s[2 * jp + 0], qfh[ks], klf[0], klf[1]);
                mma_bf16(s[2 * jp + 1], qfh[ks], klf[2], klf[3]);
                mma_bf16(s[2 * jp + 0], qfl[ks], khf[0], khf[1]);
                mma_bf16(s[2 * jp + 1], qfl[ks], khf[2], khf[3]);
            }
        }

#pragma unroll
        for (int t = 0; t < 8; t++) {
            const int j0 = kt * 64 + t * 8 + tg * 2;
            const int jr0 = j0 >> 5, jc0 = j0 & 31;
            const int jr1 = (j0 + 1) >> 5, jc1 = (j0 + 1) & 31;
            s[t][0] += bias_s[abs(ir0 - jr0) * 32 + abs(ic0 - jc0)];
            s[t][1] += bias_s[abs(ir0 - jr1) * 32 + abs(ic0 - jc1)];
            s[t][2] += bias_s[abs(ir1 - jr0) * 32 + abs(ic1 - jc0)];
            s[t][3] += bias_s[abs(ir1 - jr1) * 32 + abs(ic1 - jc1)];
        }

        float mx0 = -1e30f, mx1 = -1e30f;
#pragma unroll
        for (int t = 0; t < 8; t++) {
            mx0 = fmaxf(mx0, fmaxf(s[t][0], s[t][1]));
            mx1 = fmaxf(mx1, fmaxf(s[t][2], s[t][3]));
        }
        mx0 = fmaxf(mx0, __shfl_xor_sync(0xffffffffu, mx0, 1));
        mx0 = fmaxf(mx0, __shfl_xor_sync(0xffffffffu, mx0, 2));
        mx1 = fmaxf(mx1, __shfl_xor_sync(0xffffffffu, mx1, 1));
        mx1 = fmaxf(mx1, __shfl_xor_sync(0xffffffffu, mx1, 2));
        const float mn0 = fmaxf(mr0, mx0), mn1 = fmaxf(mr1, mx1);
        const float a0 = __expf(mr0 - mn0), a1 = __expf(mr1 - mn1);
        mr0 = mn0; mr1 = mn1;
        float sum0 = 0.f, sum1 = 0.f;
#pragma unroll
        for (int t = 0; t < 8; t++) {
            s[t][0] = __expf(s[t][0] - mn0); sum0 += s[t][0];
            s[t][1] = __expf(s[t][1] - mn0); sum0 += s[t][1];
            s[t][2] = __expf(s[t][2] - mn1); sum1 += s[t][2];
            s[t][3] = __expf(s[t][3] - mn1); sum1 += s[t][3];
        }
        sum0 += __shfl_xor_sync(0xffffffffu, sum0, 1);
        sum0 += __shfl_xor_sync(0xffffffffu, sum0, 2);
        sum1 += __shfl_xor_sync(0xffffffffu, sum1, 1);
        sum1 += __shfl_xor_sync(0xffffffffu, sum1, 2);
        lr0 = lr0 * a0 + sum0;
        lr1 = lr1 * a1 + sum1;
#pragma unroll
        for (int dt = 0; dt < 8; dt++) {
            O[dt][0] *= a0; O[dt][1] *= a0;
            O[dt][2] *= a1; O[dt][3] *= a1;
        }

#pragma unroll
        for (int js = 0; js < 4; js++) {
            uint32_t aph[4], apl[4];
            split2(s[2 * js][0],     s[2 * js][1],     aph[0], apl[0]);
            split2(s[2 * js][2],     s[2 * js][3],     aph[1], apl[1]);
            split2(s[2 * js + 1][0], s[2 * js + 1][1], aph[2], apl[2]);
            split2(s[2 * js + 1][2], s[2 * js + 1][3], aph[3], apl[3]);
#pragma unroll
            for (int dp = 0; dp < 4; dp++) {
                uint32_t vhf[4], vlf[4];
                const uint32_t off = SWZ((uint32_t)(
                    (js * 16 + (qq & 1) * 8 + l8) * 128 + dp * 32 + (qq >> 1) * 16));
                ldsm_x4_t(vhf, kb + 16384u + off);
                ldsm_x4_t(vlf, kb + 24576u + off);
                mma_bf16(O[2 * dp + 0], aph, vhf[0], vhf[1]);
                mma_bf16(O[2 * dp + 1], aph, vhf[2], vhf[3]);
                mma_bf16(O[2 * dp + 0], aph, vlf[0], vlf[1]);
                mma_bf16(O[2 * dp + 1], aph, vlf[2], vlf[3]);
                mma_bf16(O[2 * dp + 0], apl, vhf[0], vhf[1]);
                mma_bf16(O[2 * dp + 1], apl, vhf[2], vhf[3]);
            }
        }
    }
#undef ISSUE_KV

    const float inv0 = 1.f / lr0, inv1 = 1.f / lr1;
    const int t0 = qi * 128 + m0 + g;
    const size_t base0 = ((size_t)(b * 1024 + t0)) * 1024 + h * 64;
    const size_t base1 = base0 + 8 * 1024;
#pragma unroll
    for (int dt = 0; dt < 8; dt++) {
        const int d0 = dt * 8 + tg * 2;
        uint32_t h2, l2;
        split2(O[dt][0] * inv0, O[dt][1] * inv0, h2, l2);
        *(uint32_t*)(aohi + base0 + d0) = h2;
        *(uint32_t*)(aolo + base0 + d0) = l2;
        split2(O[dt][2] * inv1, O[dt][3] * inv1, h2, l2);
        *(uint32_t*)(aohi + base1 + d0) = h2;
        *(uint32_t*)(aolo + base1 + d0) = l2;
    }
}

// ---------------------------------------------------------------------------
extern "C" void kernel_launch(void* const* d_in, const int* in_sizes, int n_in,
                              void* d_out, int out_size)
{
    (void)in_sizes; (void)n_in; (void)out_size;
    const float* x      = (const float*)d_in[0];
    const float* w_qkv  = (const float*)d_in[1];
    const float* biases = (const float*)d_in[2];
    const float* w_out  = (const float*)d_in[4];
    const float* b_out  = (const float*)d_in[5];
    float* out = (float*)d_out;

    __nv_bfloat16 *qh, *ql, *kh, *kl, *vh, *vl;
    __nv_bfloat16 *ahi, *alo, *w1hi, *w1lo, *w2hi, *w2lo, *aohi, *aolo;
    cudaGetSymbolAddress((void**)&qh, g_qh);
    cudaGetSymbolAddress((void**)&ql, g_ql);
    cudaGetSymbolAddress((void**)&kh, g_kh);
    cudaGetSymbolAddress((void**)&kl, g_kl);
    cudaGetSymbolAddress((void**)&vh, g_vh);
    cudaGetSymbolAddress((void**)&vl, g_vl);
    cudaGetSymbolAddress((void**)&ahi, g_ahi);
    cudaGetSymbolAddress((void**)&alo, g_alo);
    cudaGetSymbolAddress((void**)&w1hi, g_w1hi);
    cudaGetSymbolAddress((void**)&w1lo, g_w1lo);
    cudaGetSymbolAddress((void**)&w2hi, g_w2hi);
    cudaGetSymbolAddress((void**)&w2lo, g_w2lo);
    cudaGetSymbolAddress((void**)&aohi, g_aohi);
    cudaGetSymbolAddress((void**)&aolo, g_aolo);

    cudaFuncSetAttribute(gemm_hmma<0>, cudaFuncAttributeMaxDynamicSharedMemorySize, GEMM_SMEM);
    cudaFuncSetAttribute(gemm_hmma<1>, cudaFuncAttributeMaxDynamicSharedMemorySize, GEMM_SMEM);
    cudaFuncSetAttribute(attn_tc, cudaFuncAttributeMaxDynamicSharedMemorySize, AT_SMEM);

    // 1) bf16 hi/lo splits of inputs
    split_bf16<<<8192, 256>>>(x, ahi, alo, 8192 * 1024 / 4);
    split_bf16<<<3072, 256>>>(w_qkv, w1hi, w1lo, 3072 * 1024 / 4);
    split_bf16<<<1024, 256>>>(w_out, w2hi, w2lo, 1024 * 1024 / 4);

    // 2) QKV projection (128x256 tile) -> head-major bf16 hi/lo q/k/v
    {
        dim3 grid(3072 / 256, 8192 / 128);
        gemm_hmma<0><<<grid, 256, GEMM_SMEM>>>(ahi, alo, w1hi, w1lo, nullptr, nullptr, 0,
                                               qh, ql, kh, kl, vh, vl);
    }

    // 3) Tensor-core flash attention -> aohi/aolo
    {
        dim3 grid(8, 128);
        attn_tc<<<grid, 256, AT_SMEM>>>(qh, ql, kh, kl, vh, vl, biases, aohi, aolo);
    }

    // 4) Output projection + bias -> fp32 out
    {
        dim3 grid(1024 / 256, 8192 / 128);
        gemm_hmma<1><<<grid, 256, GEMM_SMEM>>>(aohi, aolo, w2hi, w2lo, b_out, out, 1024,
                                               nullptr, nullptr, nullptr, nullptr, nullptr, nullptr);
    }
}

// round 9
// speedup vs baseline: 3.2597x; 2.1603x over previous
#include <cuda_runtime.h>
#include <cuda_fp16.h>
#include <cstdint>

#define B_ 8
#define N_ 1024
#define E_ 1024
#define H_ 16
#define D_ 64

// ---------------------------------------------------------------------------
// Static scratch (allocation-free)
// ---------------------------------------------------------------------------
#define QKV_ELEMS ((size_t)B_ * H_ * N_ * D_)
__device__ __align__(16) __half g_q[QKV_ELEMS];
__device__ __align__(16) __half g_k[QKV_ELEMS];
__device__ __align__(16) __half g_v[QKV_ELEMS];
__device__ __align__(16) __half g_x16[(size_t)8192 * 1024];
__device__ __align__(16) __half g_w1[(size_t)3072 * 1024];
__device__ __align__(16) __half g_w2[(size_t)1024 * 1024];
__device__ __align__(16) __half g_ao[(size_t)8192 * 1024];

__device__ __forceinline__ uint32_t smem_to_u32(const void* p) {
    uint32_t a;
    asm("{ .reg .u64 t; cvta.to.shared.u64 t, %1; cvt.u32.u64 %0, t; }" : "=r"(a) : "l"(p));
    return a;
}
#define SWZ(o) ((o) ^ (((o) >> 3) & 0x70))

__device__ __forceinline__ void ldsm_x4(uint32_t* d, uint32_t addr) {
    asm volatile("ldmatrix.sync.aligned.m8n8.x4.shared.b16 {%0,%1,%2,%3}, [%4];"
                 : "=r"(d[0]), "=r"(d[1]), "=r"(d[2]), "=r"(d[3]) : "r"(addr));
}
__device__ __forceinline__ void ldsm_x4_t(uint32_t* d, uint32_t addr) {
    asm volatile("ldmatrix.sync.aligned.m8n8.x4.trans.shared.b16 {%0,%1,%2,%3}, [%4];"
                 : "=r"(d[0]), "=r"(d[1]), "=r"(d[2]), "=r"(d[3]) : "r"(addr));
}
__device__ __forceinline__ void mma_f16(float* c, const uint32_t* a, uint32_t b0, uint32_t b1) {
    asm volatile(
        "mma.sync.aligned.m16n8k16.row.col.f32.f16.f16.f32 "
        "{%0,%1,%2,%3}, {%4,%5,%6,%7}, {%8,%9}, {%0,%1,%2,%3};"
        : "+f"(c[0]), "+f"(c[1]), "+f"(c[2]), "+f"(c[3])
        : "r"(a[0]), "r"(a[1]), "r"(a[2]), "r"(a[3]), "r"(b0), "r"(b1));
}
__device__ __forceinline__ void cp_async16(uint32_t sdst, const void* gsrc) {
    asm volatile("cp.async.cg.shared.global [%0], [%1], 16;" :: "r"(sdst), "l"(gsrc));
}
#define CP_COMMIT() asm volatile("cp.async.commit_group;" ::: "memory")
#define CP_WAIT_ALL() asm volatile("cp.async.wait_group 0;" ::: "memory")

__device__ __forceinline__ uint32_t pack2h(float a, float b) {
    __half2 h = __floats2half2_rn(a, b);
    return *reinterpret_cast<uint32_t*>(&h);
}

// ---------------------------------------------------------------------------
// fp32 -> fp16 convert
// ---------------------------------------------------------------------------
__global__ __launch_bounds__(256) void to_fp16(
    const float* __restrict__ x, __half* __restrict__ y, int n4)
{
    int i = blockIdx.x * 256 + threadIdx.x;
    if (i >= n4) return;
    float4 v = ((const float4*)x)[i];
    uint2 o;
    o.x = pack2h(v.x, v.y);
    o.y = pack2h(v.z, v.w);
    ((uint2*)y)[i] = o;
}

// ---------------------------------------------------------------------------
// fp16 HMMA GEMM (NT), K=1024, 128x256 CTA tile, 256 threads,
// 8 warps in 2(m) x 4(n), warp tile 64x64. BK=64, cp.async double buffer.
// MODE 0: scatter q/k/v fp16 head-major; q scaled 0.125
// MODE 1: C = acc + bias[n] -> fp32 out
// ---------------------------------------------------------------------------
#define STAGE_BYTES 49152u
#define GEMM_SMEM (2 * 49152)

template <int MODE>
__global__ __launch_bounds__(256, 1)
void gemm_hmma(const __half* __restrict__ A, const __half* __restrict__ Bm,
               const float* __restrict__ bias, float* __restrict__ C, int ldc,
               __half* __restrict__ OQ, __half* __restrict__ OK, __half* __restrict__ OV)
{
    extern __shared__ char smem[];
    const uint32_t sb = smem_to_u32(smem);
    const int tid = threadIdx.x;
    const int wid = tid >> 5, lane = tid & 31;
    const int bm = blockIdx.y * 128, bn = blockIdx.x * 256;
    const int wm = wid >> 2, wn = wid & 3;   // 2m x 4n warps

    const __half* tA = A + (size_t)bm * 1024;
    const __half* tB = Bm + (size_t)bn * 1024;

    const int q = lane >> 3, l8 = lane & 7;
    const int ar = wm * 64 + (q & 1) * 8 + l8;    // + mt*16
    const int ac = (q >> 1) * 16;                 // + ks*32 (bytes)
    const int br = wn * 64 + (q >> 1) * 8 + l8;   // + jp*16
    const int bc = (q & 1) * 16;                  // + ks*32 (bytes)

    float acc[4][8][4];
#pragma unroll
    for (int mt = 0; mt < 4; mt++)
#pragma unroll
        for (int nt = 0; nt < 8; nt++)
#pragma unroll
            for (int e = 0; e < 4; e++) acc[mt][nt][e] = 0.f;

    // stage layout: A 16KB | B 32KB
#define ISSUE(kc_, buf_) do {                                                     \
    const uint32_t stage = sb + (uint32_t)(buf_) * STAGE_BYTES;                   \
    {                                                                             \
        const __half* gp = tA + (size_t)(kc_) * 64;                               \
        _Pragma("unroll")                                                         \
        for (int i2 = 0; i2 < 4; i2++) {                                          \
            const int idx = tid + 256 * i2;                                       \
            const int r = idx >> 3, c = idx & 7;                                  \
            cp_async16(stage + SWZ((uint32_t)(r * 128 + c * 16)),                 \
                       gp + (size_t)r * 1024 + c * 8);                            \
        }                                                                         \
    }                                                                             \
    {                                                                             \
        const __half* gp = tB + (size_t)(kc_) * 64;                               \
        _Pragma("unroll")                                                         \
        for (int i2 = 0; i2 < 8; i2++) {                                          \
            const int idx = tid + 256 * i2;                                       \
            const int r = idx >> 3, c = idx & 7;                                  \
            cp_async16(stage + 16384u + SWZ((uint32_t)(r * 128 + c * 16)),        \
                       gp + (size_t)r * 1024 + c * 8);                            \
        }                                                                         \
    }                                                                             \
    CP_COMMIT();                                                                  \
} while (0)

    ISSUE(0, 0);

    for (int kc = 0; kc < 16; kc++) {
        const int buf = kc & 1;
        CP_WAIT_ALL();
        __syncthreads();
        if (kc < 15) ISSUE(kc + 1, buf ^ 1);

        const uint32_t stage = sb + (uint32_t)buf * STAGE_BYTES;
        const uint32_t sA = stage, sB = stage + 16384u;

#pragma unroll
        for (int ks = 0; ks < 4; ks++) {
            uint32_t af[4][4];
#pragma unroll
            for (int mt = 0; mt < 4; mt++) {
                const uint32_t off = SWZ((uint32_t)((ar + mt * 16) * 128 + ac + ks * 32));
                ldsm_x4(af[mt], sA + off);
            }
#pragma unroll
            for (int jp = 0; jp < 4; jp++) {
                uint32_t bf[4];
                const uint32_t off = SWZ((uint32_t)((br + jp * 16) * 128 + bc + ks * 32));
                ldsm_x4(bf, sB + off);
#pragma unroll
                for (int mt = 0; mt < 4; mt++) {
                    mma_f16(acc[mt][2 * jp + 0], af[mt], bf[0], bf[1]);
                    mma_f16(acc[mt][2 * jp + 1], af[mt], bf[2], bf[3]);
                }
            }
        }
    }
#undef ISSUE

    const int g = lane >> 2, tg = lane & 3;
    if (MODE == 0) {
        const int which = bn >> 10;
        __half* dst = (which == 0) ? OQ : ((which == 1) ? OK : OV);
        const float sc = (which == 0) ? 0.125f : 1.0f;
#pragma unroll
        for (int mt = 0; mt < 4; mt++) {
            const int row0 = bm + wm * 64 + mt * 16 + g;
            const int bidx = row0 >> 10, tt = row0 & 1023;
#pragma unroll
            for (int nt = 0; nt < 8; nt++) {
                const int col = bn + wn * 64 + nt * 8 + tg * 2;
                const int e = col & 1023, hh = e >> 6, dd = e & 63;
                const size_t i0 = (((size_t)bidx * 16 + hh) * 1024 + tt) * 64 + dd;
                *(uint32_t*)(dst + i0) =
                    pack2h(acc[mt][nt][0] * sc, acc[mt][nt][1] * sc);
                *(uint32_t*)(dst + i0 + 8 * 64) =
                    pack2h(acc[mt][nt][2] * sc, acc[mt][nt][3] * sc);
            }
        }
    } else {
#pragma unroll
        for (int mt = 0; mt < 4; mt++) {
            const int row0 = bm + wm * 64 + mt * 16 + g;
#pragma unroll
            for (int nt = 0; nt < 8; nt++) {
                const int col = bn + wn * 64 + nt * 8 + tg * 2;
                const float b0v = bias[col], b1v = bias[col + 1];
                *(float2*)(C + (size_t)row0 * ldc + col) =
                    make_float2(acc[mt][nt][0] + b0v, acc[mt][nt][1] + b1v);
                *(float2*)(C + (size_t)(row0 + 8) * ldc + col) =
                    make_float2(acc[mt][nt][2] + b0v, acc[mt][nt][3] + b1v);
            }
        }
    }
}

// ---------------------------------------------------------------------------
// fp16 tensor-core flash attention (single-term MMAs).
// One CTA per (bh, 128-query tile). 8 warps, each owns 16 query rows.
// smem: bias 4KB @0 | Q 16KB @4096 | KV double buffer 2x16KB @20480.
// ---------------------------------------------------------------------------
#define AT_QOFF 4096u
#define AT_KVOFF 20480u
#define AT_SMEM (4096 + 16384 + 32768)

__global__ __launch_bounds__(256, 1) void attn_tc(
    const __half* __restrict__ q_, const __half* __restrict__ k_,
    const __half* __restrict__ v_, const float* __restrict__ biases,
    __half* __restrict__ ao)
{
    extern __shared__ char smem[];
    const uint32_t sb = smem_to_u32(smem);
    const int tid = threadIdx.x, wid = tid >> 5, lane = tid & 31;
    const int g = lane >> 2, tg = lane & 3, qq = lane >> 3, l8 = lane & 7;
    const int qi = blockIdx.x, bh = blockIdx.y;
    const int b = bh >> 4, h = bh & 15;
    const int m0 = wid * 16;
    const size_t hb = (size_t)bh << 16;

    float* bias_s = (float*)smem;
    for (int i = tid; i < 1024; i += 256) bias_s[i] = biases[h * 1024 + i];

    // stage Q: 128 rows x 64 fp16, SW128
    {
        const __half* src = q_ + hb + (size_t)(qi * 128) * 64;
#pragma unroll
        for (int i2 = 0; i2 < 4; i2++) {
            const int idx = tid + 256 * i2;
            const int r = idx >> 3, c = idx & 7;
            cp_async16(sb + AT_QOFF + SWZ((uint32_t)(r * 128 + c * 16)),
                       src + (size_t)r * 64 + c * 8);
        }
        CP_COMMIT();
    }

    const __half* kvp[2] = { k_ + hb, v_ + hb };

#define ISSUE_KV(kt_, buf_) do {                                                  \
    const uint32_t st = sb + AT_KVOFF + (uint32_t)(buf_) * 16384u;                \
    _Pragma("unroll")                                                             \
    for (int t = 0; t < 2; t++) {                                                 \
        const __half* gp = kvp[t] + (size_t)((kt_) * 64) * 64;                    \
        _Pragma("unroll")                                                         \
        for (int i2 = 0; i2 < 2; i2++) {                                          \
            const int idx = tid + 256 * i2;                                       \
            const int r = idx >> 3, c = idx & 7;                                  \
            cp_async16(st + t * 8192u + SWZ((uint32_t)(r * 128 + c * 16)),        \
                       gp + (size_t)r * 64 + c * 8);                              \
        }                                                                         \
    }                                                                             \
    CP_COMMIT();                                                                  \
} while (0)

    ISSUE_KV(0, 0);
    CP_WAIT_ALL();
    __syncthreads();

    // Q fragments resident (4 k-steps)
    uint32_t qf[4][4];
#pragma unroll
    for (int ks = 0; ks < 4; ks++) {
        const uint32_t off =
            SWZ((uint32_t)((m0 + (qq & 1) * 8 + l8) * 128 + (qq >> 1) * 16 + ks * 32));
        ldsm_x4(qf[ks], sb + AT_QOFF + off);
    }

    float O[8][4];
#pragma unroll
    for (int dt = 0; dt < 8; dt++)
#pragma unroll
        for (int e = 0; e < 4; e++) O[dt][e] = 0.f;
    float mr0 = -1e30f, mr1 = -1e30f, lr0 = 0.f, lr1 = 0.f;

    const int i0 = qi * 128 + m0 + g;
    const int ir0 = i0 >> 5, ic0 = i0 & 31;
    const int ir1 = (i0 + 8) >> 5, ic1 = (i0 + 8) & 31;

    for (int kt = 0; kt < 16; kt++) {
        if (kt > 0) { CP_WAIT_ALL(); __syncthreads(); }
        if (kt < 15) ISSUE_KV(kt + 1, (kt + 1) & 1);
        const uint32_t kb = sb + AT_KVOFF + (uint32_t)(kt & 1) * 16384u;

        // ---- S = Q K^T ----
        float s[8][4];
#pragma unroll
        for (int t = 0; t < 8; t++)
#pragma unroll
            for (int e = 0; e < 4; e++) s[t][e] = 0.f;

#pragma unroll
        for (int ks = 0; ks < 4; ks++) {
#pragma unroll
            for (int jp = 0; jp < 4; jp++) {
                uint32_t kf[4];
                const uint32_t off = SWZ((uint32_t)(
                    ((qq >> 1) * 8 + l8 + jp * 16) * 128 + (qq & 1) * 16 + ks * 32));
                ldsm_x4(kf, kb + off);
                mma_f16(s[2 * jp + 0], qf[ks], kf[0], kf[1]);
                mma_f16(s[2 * jp + 1], qf[ks], kf[2], kf[3]);
            }
        }

        // ---- relative-position bias ----
#pragma unroll
        for (int t = 0; t < 8; t++) {
            const int j0 = kt * 64 + t * 8 + tg * 2;
            const int jr0 = j0 >> 5, jc0 = j0 & 31;
            const int jr1 = (j0 + 1) >> 5, jc1 = (j0 + 1) & 31;
            s[t][0] += bias_s[abs(ir0 - jr0) * 32 + abs(ic0 - jc0)];
            s[t][1] += bias_s[abs(ir0 - jr1) * 32 + abs(ic0 - jc1)];
            s[t][2] += bias_s[abs(ir1 - jr0) * 32 + abs(ic1 - jc0)];
            s[t][3] += bias_s[abs(ir1 - jr1) * 32 + abs(ic1 - jc1)];
        }

        // ---- online softmax ----
        float mx0 = -1e30f, mx1 = -1e30f;
#pragma unroll
        for (int t = 0; t < 8; t++) {
            mx0 = fmaxf(mx0, fmaxf(s[t][0], s[t][1]));
            mx1 = fmaxf(mx1, fmaxf(s[t][2], s[t][3]));
        }
        mx0 = fmaxf(mx0, __shfl_xor_sync(0xffffffffu, mx0, 1));
        mx0 = fmaxf(mx0, __shfl_xor_sync(0xffffffffu, mx0, 2));
        mx1 = fmaxf(mx1, __shfl_xor_sync(0xffffffffu, mx1, 1));
        mx1 = fmaxf(mx1, __shfl_xor_sync(0xffffffffu, mx1, 2));
        const float mn0 = fmaxf(mr0, mx0), mn1 = fmaxf(mr1, mx1);
        const float a0 = __expf(mr0 - mn0), a1 = __expf(mr1 - mn1);
        mr0 = mn0; mr1 = mn1;
        float sum0 = 0.f, sum1 = 0.f;
#pragma unroll
        for (int t = 0; t < 8; t++) {
            s[t][0] = __expf(s[t][0] - mn0); sum0 += s[t][0];
            s[t][1] = __expf(s[t][1] - mn0); sum0 += s[t][1];
            s[t][2] = __expf(s[t][2] - mn1); sum1 += s[t][2];
            s[t][3] = __expf(s[t][3] - mn1); sum1 += s[t][3];
        }
        sum0 += __shfl_xor_sync(0xffffffffu, sum0, 1);
        sum0 += __shfl_xor_sync(0xffffffffu, sum0, 2);
        sum1 += __shfl_xor_sync(0xffffffffu, sum1, 1);
        sum1 += __shfl_xor_sync(0xffffffffu, sum1, 2);
        lr0 = lr0 * a0 + sum0;
        lr1 = lr1 * a1 + sum1;
#pragma unroll
        for (int dt = 0; dt < 8; dt++) {
            O[dt][0] *= a0; O[dt][1] *= a0;
            O[dt][2] *= a1; O[dt][3] *= a1;
        }

        // ---- O += P V (P packed to fp16 A fragments in registers) ----
#pragma unroll
        for (int js = 0; js < 4; js++) {
            uint32_t ap[4];
            ap[0] = pack2h(s[2 * js][0],     s[2 * js][1]);
            ap[1] = pack2h(s[2 * js][2],     s[2 * js][3]);
            ap[2] = pack2h(s[2 * js + 1][0], s[2 * js + 1][1]);
            ap[3] = pack2h(s[2 * js + 1][2], s[2 * js + 1][3]);
#pragma unroll
            for (int dp = 0; dp < 4; dp++) {
                uint32_t vf[4];
                const uint32_t off = SWZ((uint32_t)(
                    (js * 16 + (qq & 1) * 8 + l8) * 128 + dp * 32 + (qq >> 1) * 16));
                ldsm_x4_t(vf, kb + 8192u + off);
                mma_f16(O[2 * dp + 0], ap, vf[0], vf[1]);
                mma_f16(O[2 * dp + 1], ap, vf[2], vf[3]);
            }
        }
    }
#undef ISSUE_KV

    // ---- epilogue: normalize, fp16, token-major out ----
    const float inv0 = 1.f / lr0, inv1 = 1.f / lr1;
    const int t0 = qi * 128 + m0 + g;
    const size_t base0 = ((size_t)(b * 1024 + t0)) * 1024 + h * 64;
    const size_t base1 = base0 + 8 * 1024;
#pragma unroll
    for (int dt = 0; dt < 8; dt++) {
        const int d0 = dt * 8 + tg * 2;
        *(uint32_t*)(ao + base0 + d0) = pack2h(O[dt][0] * inv0, O[dt][1] * inv0);
        *(uint32_t*)(ao + base1 + d0) = pack2h(O[dt][2] * inv1, O[dt][3] * inv1);
    }
}

// ---------------------------------------------------------------------------
extern "C" void kernel_launch(void* const* d_in, const int* in_sizes, int n_in,
                              void* d_out, int out_size)
{
    (void)in_sizes; (void)n_in; (void)out_size;
    const float* x      = (const float*)d_in[0];
    const float* w_qkv  = (const float*)d_in[1];
    const float* biases = (const float*)d_in[2];
    const float* w_out  = (const float*)d_in[4];
    const float* b_out  = (const float*)d_in[5];
    float* out = (float*)d_out;

    __half *q, *k, *v, *x16, *w1, *w2, *ao;
    cudaGetSymbolAddress((void**)&q, g_q);
    cudaGetSymbolAddress((void**)&k, g_k);
    cudaGetSymbolAddress((void**)&v, g_v);
    cudaGetSymbolAddress((void**)&x16, g_x16);
    cudaGetSymbolAddress((void**)&w1, g_w1);
    cudaGetSymbolAddress((void**)&w2, g_w2);
    cudaGetSymbolAddress((void**)&ao, g_ao);

    cudaFuncSetAttribute(gemm_hmma<0>, cudaFuncAttributeMaxDynamicSharedMemorySize, GEMM_SMEM);
    cudaFuncSetAttribute(gemm_hmma<1>, cudaFuncAttributeMaxDynamicSharedMemorySize, GEMM_SMEM);
    cudaFuncSetAttribute(attn_tc, cudaFuncAttributeMaxDynamicSharedMemorySize, AT_SMEM);

    // 1) fp16 converts of inputs
    to_fp16<<<8192, 256>>>(x, x16, 8192 * 1024 / 4);
    to_fp16<<<3072, 256>>>(w_qkv, w1, 3072 * 1024 / 4);
    to_fp16<<<1024, 256>>>(w_out, w2, 1024 * 1024 / 4);

    // 2) QKV projection -> head-major fp16 q/k/v (q pre-scaled)
    {
        dim3 grid(3072 / 256, 8192 / 128);
        gemm_hmma<0><<<grid, 256, GEMM_SMEM>>>(x16, w1, nullptr, nullptr, 0, q, k, v);
    }

    // 3) fp16 tensor-core flash attention -> ao
    {
        dim3 grid(8, 128);
        attn_tc<<<grid, 256, AT_SMEM>>>(q, k, v, biases, ao);
    }

    // 4) Output projection + bias -> fp32 out
    {
        dim3 grid(1024 / 256, 8192 / 128);
        gemm_hmma<1><<<grid, 256, GEMM_SMEM>>>(ao, w2, b_out, out, 1024,
                                               nullptr, nullptr, nullptr);
    }
}

// round 10
// speedup vs baseline: 3.4106x; 1.0463x over previous
#include <cuda_runtime.h>
#include <cuda_fp16.h>
#include <cstdint>

#define B_ 8
#define N_ 1024
#define E_ 1024
#define H_ 16
#define D_ 64

// ---------------------------------------------------------------------------
// Static scratch (allocation-free)
// ---------------------------------------------------------------------------
#define QKV_ELEMS ((size_t)B_ * H_ * N_ * D_)
__device__ __align__(16) __half g_q[QKV_ELEMS];
__device__ __align__(16) __half g_k[QKV_ELEMS];
__device__ __align__(16) __half g_v[QKV_ELEMS];
__device__ __align__(16) __half g_x16[(size_t)8192 * 1024];
__device__ __align__(16) __half g_w1[(size_t)3072 * 1024];
__device__ __align__(16) __half g_w2[(size_t)1024 * 1024];
__device__ __align__(16) __half g_ao[(size_t)8192 * 1024];

__device__ __forceinline__ uint32_t smem_to_u32(const void* p) {
    uint32_t a;
    asm("{ .reg .u64 t; cvta.to.shared.u64 t, %1; cvt.u32.u64 %0, t; }" : "=r"(a) : "l"(p));
    return a;
}
#define SWZ(o) ((o) ^ (((o) >> 3) & 0x70))

__device__ __forceinline__ void ldsm_x4(uint32_t* d, uint32_t addr) {
    asm volatile("ldmatrix.sync.aligned.m8n8.x4.shared.b16 {%0,%1,%2,%3}, [%4];"
                 : "=r"(d[0]), "=r"(d[1]), "=r"(d[2]), "=r"(d[3]) : "r"(addr));
}
__device__ __forceinline__ void ldsm_x4_t(uint32_t* d, uint32_t addr) {
    asm volatile("ldmatrix.sync.aligned.m8n8.x4.trans.shared.b16 {%0,%1,%2,%3}, [%4];"
                 : "=r"(d[0]), "=r"(d[1]), "=r"(d[2]), "=r"(d[3]) : "r"(addr));
}
__device__ __forceinline__ void mma_f16(float* c, const uint32_t* a, uint32_t b0, uint32_t b1) {
    asm volatile(
        "mma.sync.aligned.m16n8k16.row.col.f32.f16.f16.f32 "
        "{%0,%1,%2,%3}, {%4,%5,%6,%7}, {%8,%9}, {%0,%1,%2,%3};"
        : "+f"(c[0]), "+f"(c[1]), "+f"(c[2]), "+f"(c[3])
        : "r"(a[0]), "r"(a[1]), "r"(a[2]), "r"(a[3]), "r"(b0), "r"(b1));
}
__device__ __forceinline__ void cp_async16(uint32_t sdst, const void* gsrc) {
    asm volatile("cp.async.cg.shared.global [%0], [%1], 16;" :: "r"(sdst), "l"(gsrc));
}
#define CP_COMMIT() asm volatile("cp.async.commit_group;" ::: "memory")
#define CP_WAIT_ALL() asm volatile("cp.async.wait_group 0;" ::: "memory")
#define CP_WAIT_1() asm volatile("cp.async.wait_group 1;" ::: "memory")

__device__ __forceinline__ uint32_t pack2h(float a, float b) {
    __half2 h = __floats2half2_rn(a, b);
    return *reinterpret_cast<uint32_t*>(&h);
}

// ---------------------------------------------------------------------------
// fp32 -> fp16 convert
// ---------------------------------------------------------------------------
__global__ __launch_bounds__(256) void to_fp16(
    const float* __restrict__ x, __half* __restrict__ y, int n4)
{
    int i = blockIdx.x * 256 + threadIdx.x;
    if (i >= n4) return;
    float4 v = ((const float4*)x)[i];
    uint2 o;
    o.x = pack2h(v.x, v.y);
    o.y = pack2h(v.z, v.w);
    ((uint2*)y)[i] = o;
}

// ---------------------------------------------------------------------------
// fp16 HMMA GEMM (NT), K=1024, 128x256 CTA tile, 256 threads,
// 8 warps in 2(m) x 4(n), warp tile 64x64. BK=64, 3-stage cp.async pipeline.
// MODE 0: scatter q/k/v fp16 head-major; q scaled 0.125
// MODE 1: C = acc + bias[n] -> fp32 out
// ---------------------------------------------------------------------------
#define STAGE_BYTES 49152u
#define GEMM_SMEM (3 * 49152)

template <int MODE>
__global__ __launch_bounds__(256, 1)
void gemm_hmma(const __half* __restrict__ A, const __half* __restrict__ Bm,
               const float* __restrict__ bias, float* __restrict__ C, int ldc,
               __half* __restrict__ OQ, __half* __restrict__ OK, __half* __restrict__ OV)
{
    extern __shared__ char smem[];
    const uint32_t sb = smem_to_u32(smem);
    const int tid = threadIdx.x;
    const int wid = tid >> 5, lane = tid & 31;
    const int bm = blockIdx.y * 128, bn = blockIdx.x * 256;
    const int wm = wid >> 2, wn = wid & 3;   // 2m x 4n warps

    const __half* tA = A + (size_t)bm * 1024;
    const __half* tB = Bm + (size_t)bn * 1024;

    const int q = lane >> 3, l8 = lane & 7;
    const int ar = wm * 64 + (q & 1) * 8 + l8;    // + mt*16
    const int ac = (q >> 1) * 16;                 // + ks*32 (bytes)
    const int br = wn * 64 + (q >> 1) * 8 + l8;   // + jp*16
    const int bc = (q & 1) * 16;                  // + ks*32 (bytes)

    float acc[4][8][4];
#pragma unroll
    for (int mt = 0; mt < 4; mt++)
#pragma unroll
        for (int nt = 0; nt < 8; nt++)
#pragma unroll
            for (int e = 0; e < 4; e++) acc[mt][nt][e] = 0.f;

    // stage layout: A 16KB | B 32KB
#define ISSUE(kc_, buf_) do {                                                     \
    const uint32_t stage = sb + (uint32_t)(buf_) * STAGE_BYTES;                   \
    {                                                                             \
        const __half* gp = tA + (size_t)(kc_) * 64;                               \
        _Pragma("unroll")                                                         \
        for (int i2 = 0; i2 < 4; i2++) {                                          \
            const int idx = tid + 256 * i2;                                       \
            const int r = idx >> 3, c = idx & 7;                                  \
            cp_async16(stage + SWZ((uint32_t)(r * 128 + c * 16)),                 \
                       gp + (size_t)r * 1024 + c * 8);                            \
        }                                                                         \
    }                                                                             \
    {                                                                             \
        const __half* gp = tB + (size_t)(kc_) * 64;                               \
        _Pragma("unroll")                                                         \
        for (int i2 = 0; i2 < 8; i2++) {                                          \
            const int idx = tid + 256 * i2;                                       \
            const int r = idx >> 3, c = idx & 7;                                  \
            cp_async16(stage + 16384u + SWZ((uint32_t)(r * 128 + c * 16)),        \
                       gp + (size_t)r * 1024 + c * 8);                            \
        }                                                                         \
    }                                                                             \
    CP_COMMIT();                                                                  \
} while (0)

    ISSUE(0, 0);
    ISSUE(1, 1);

    int buf = 0;
    for (int kc = 0; kc < 16; kc++) {
        if (kc == 15) CP_WAIT_ALL(); else CP_WAIT_1();
        __syncthreads();
        if (kc < 14) {
            const int nb = (buf + 2 >= 3) ? buf - 1 : buf + 2;
            ISSUE(kc + 2, nb);
        }

        const uint32_t stage = sb + (uint32_t)buf * STAGE_BYTES;
        const uint32_t sA = stage, sB = stage + 16384u;

#pragma unroll
        for (int ks = 0; ks < 4; ks++) {
            uint32_t af[4][4];
#pragma unroll
            for (int mt = 0; mt < 4; mt++) {
                const uint32_t off = SWZ((uint32_t)((ar + mt * 16) * 128 + ac + ks * 32));
                ldsm_x4(af[mt], sA + off);
            }
#pragma unroll
            for (int jp = 0; jp < 4; jp++) {
                uint32_t bf[4];
                const uint32_t off = SWZ((uint32_t)((br + jp * 16) * 128 + bc + ks * 32));
                ldsm_x4(bf, sB + off);
#pragma unroll
                for (int mt = 0; mt < 4; mt++) {
                    mma_f16(acc[mt][2 * jp + 0], af[mt], bf[0], bf[1]);
                    mma_f16(acc[mt][2 * jp + 1], af[mt], bf[2], bf[3]);
                }
            }
        }
        buf = (buf + 1 >= 3) ? 0 : buf + 1;
    }
#undef ISSUE

    const int g = lane >> 2, tg = lane & 3;
    if (MODE == 0) {
        const int which = bn >> 10;
        __half* dst = (which == 0) ? OQ : ((which == 1) ? OK : OV);
        const float sc = (which == 0) ? 0.125f : 1.0f;
#pragma unroll
        for (int mt = 0; mt < 4; mt++) {
            const int row0 = bm + wm * 64 + mt * 16 + g;
            const int bidx = row0 >> 10, tt = row0 & 1023;
#pragma unroll
            for (int nt = 0; nt < 8; nt++) {
                const int col = bn + wn * 64 + nt * 8 + tg * 2;
                const int e = col & 1023, hh = e >> 6, dd = e & 63;
                const size_t i0 = (((size_t)bidx * 16 + hh) * 1024 + tt) * 64 + dd;
                *(uint32_t*)(dst + i0) =
                    pack2h(acc[mt][nt][0] * sc, acc[mt][nt][1] * sc);
                *(uint32_t*)(dst + i0 + 8 * 64) =
                    pack2h(acc[mt][nt][2] * sc, acc[mt][nt][3] * sc);
            }
        }
    } else {
#pragma unroll
        for (int mt = 0; mt < 4; mt++) {
            const int row0 = bm + wm * 64 + mt * 16 + g;
#pragma unroll
            for (int nt = 0; nt < 8; nt++) {
                const int col = bn + wn * 64 + nt * 8 + tg * 2;
                const float b0v = bias[col], b1v = bias[col + 1];
                *(float2*)(C + (size_t)row0 * ldc + col) =
                    make_float2(acc[mt][nt][0] + b0v, acc[mt][nt][1] + b1v);
                *(float2*)(C + (size_t)(row0 + 8) * ldc + col) =
                    make_float2(acc[mt][nt][2] + b0v, acc[mt][nt][3] + b1v);
            }
        }
    }
}

// ---------------------------------------------------------------------------
// fp16 tensor-core flash attention, 3-stage KV pipeline, 2 CTAs/SM.
// smem: bias 4KB @0 | Q 16KB @4096 | KV 3x16KB @20480  (= 68KB)
// ---------------------------------------------------------------------------
#define AT_QOFF 4096u
#define AT_KVOFF 20480u
#define AT_SMEM (4096 + 16384 + 3 * 16384)

__global__ __launch_bounds__(256, 2) void attn_tc(
    const __half* __restrict__ q_, const __half* __restrict__ k_,
    const __half* __restrict__ v_, const float* __restrict__ biases,
    __half* __restrict__ ao)
{
    extern __shared__ char smem[];
    const uint32_t sb = smem_to_u32(smem);
    const int tid = threadIdx.x, wid = tid >> 5, lane = tid & 31;
    const int g = lane >> 2, tg = lane & 3, qq = lane >> 3, l8 = lane & 7;
    const int qi = blockIdx.x, bh = blockIdx.y;
    const int b = bh >> 4, h = bh & 15;
    const int m0 = wid * 16;
    const size_t hb = (size_t)bh << 16;

    float* bias_s = (float*)smem;
    for (int i = tid; i < 1024; i += 256) bias_s[i] = biases[h * 1024 + i];

    // group 0: Q (128 x 64 fp16, SW128)
    {
        const __half* src = q_ + hb + (size_t)(qi * 128) * 64;
#pragma unroll
        for (int i2 = 0; i2 < 4; i2++) {
            const int idx = tid + 256 * i2;
            const int r = idx >> 3, c = idx & 7;
            cp_async16(sb + AT_QOFF + SWZ((uint32_t)(r * 128 + c * 16)),
                       src + (size_t)r * 64 + c * 8);
        }
        CP_COMMIT();
    }

    const __half* kvp[2] = { k_ + hb, v_ + hb };

#define ISSUE_KV(kt_, buf_) do {                                                  \
    const uint32_t st = sb + AT_KVOFF + (uint32_t)(buf_) * 16384u;                \
    _Pragma("unroll")                                                             \
    for (int t = 0; t < 2; t++) {                                                 \
        const __half* gp = kvp[t] + (size_t)((kt_) * 64) * 64;                    \
        _Pragma("unroll")                                                         \
        for (int i2 = 0; i2 < 2; i2++) {                                          \
            const int idx = tid + 256 * i2;                                       \
            const int r = idx >> 3, c = idx & 7;                                  \
            cp_async16(st + t * 8192u + SWZ((uint32_t)(r * 128 + c * 16)),        \
                       gp + (size_t)r * 64 + c * 8);                              \
        }                                                                         \
    }                                                                             \
    CP_COMMIT();                                                                  \
} while (0)

    ISSUE_KV(0, 0);   // group 1
    ISSUE_KV(1, 1);   // group 2
    CP_WAIT_1();      // Q + KV0 complete (KV1 may be in flight)
    __syncthreads();

    // Q fragments resident (4 k-steps)
    uint32_t qf[4][4];
#pragma unroll
    for (int ks = 0; ks < 4; ks++) {
        const uint32_t off =
            SWZ((uint32_t)((m0 + (qq & 1) * 8 + l8) * 128 + (qq >> 1) * 16 + ks * 32));
        ldsm_x4(qf[ks], sb + AT_QOFF + off);
    }

    float O[8][4];
#pragma unroll
    for (int dt = 0; dt < 8; dt++)
#pragma unroll
        for (int e = 0; e < 4; e++) O[dt][e] = 0.f;
    float mr0 = -1e30f, mr1 = -1e30f, lr0 = 0.f, lr1 = 0.f;

    const int i0 = qi * 128 + m0 + g;
    const int ir0 = i0 >> 5, ic0 = i0 & 31;
    const int ir1 = (i0 + 8) >> 5, ic1 = (i0 + 8) & 31;

    int buf = 0;
    for (int kt = 0; kt < 16; kt++) {
        if (kt > 0) {
            if (kt == 15) CP_WAIT_ALL(); else CP_WAIT_1();
            __syncthreads();
        }
        if (kt < 14) {
            const int nb = (buf + 2 >= 3) ? buf - 1 : buf + 2;
            ISSUE_KV(kt + 2, nb);
        }
        const uint32_t kb = sb + AT_KVOFF + (uint32_t)buf * 16384u;

        // ---- S = Q K^T ----
        float s[8][4];
#pragma unroll
        for (int t = 0; t < 8; t++)
#pragma unroll
            for (int e = 0; e < 4; e++) s[t][e] = 0.f;

#pragma unroll
        for (int ks = 0; ks < 4; ks++) {
#pragma unroll
            for (int jp = 0; jp < 4; jp++) {
                uint32_t kf[4];
                const uint32_t off = SWZ((uint32_t)(
                    ((qq >> 1) * 8 + l8 + jp * 16) * 128 + (qq & 1) * 16 + ks * 32));
                ldsm_x4(kf, kb + off);
                mma_f16(s[2 * jp + 0], qf[ks], kf[0], kf[1]);
                mma_f16(s[2 * jp + 1], qf[ks], kf[2], kf[3]);
            }
        }

        // ---- relative-position bias ----
#pragma unroll
        for (int t = 0; t < 8; t++) {
            const int j0 = kt * 64 + t * 8 + tg * 2;
            const int jr0 = j0 >> 5, jc0 = j0 & 31;
            const int jr1 = (j0 + 1) >> 5, jc1 = (j0 + 1) & 31;
            s[t][0] += bias_s[abs(ir0 - jr0) * 32 + abs(ic0 - jc0)];
            s[t][1] += bias_s[abs(ir0 - jr1) * 32 + abs(ic0 - jc1)];
            s[t][2] += bias_s[abs(ir1 - jr0) * 32 + abs(ic1 - jc0)];
            s[t][3] += bias_s[abs(ir1 - jr1) * 32 + abs(ic1 - jc1)];
        }

        // ---- online softmax ----
        float mx0 = -1e30f, mx1 = -1e30f;
#pragma unroll
        for (int t = 0; t < 8; t++) {
            mx0 = fmaxf(mx0, fmaxf(s[t][0], s[t][1]));
            mx1 = fmaxf(mx1, fmaxf(s[t][2], s[t][3]));
        }
        mx0 = fmaxf(mx0, __shfl_xor_sync(0xffffffffu, mx0, 1));
        mx0 = fmaxf(mx0, __shfl_xor_sync(0xffffffffu, mx0, 2));
        mx1 = fmaxf(mx1, __shfl_xor_sync(0xffffffffu, mx1, 1));
        mx1 = fmaxf(mx1, __shfl_xor_sync(0xffffffffu, mx1, 2));
        const float mn0 = fmaxf(mr0, mx0), mn1 = fmaxf(mr1, mx1);
        const float a0 = __expf(mr0 - mn0), a1 = __expf(mr1 - mn1);
        mr0 = mn0; mr1 = mn1;
        float sum0 = 0.f, sum1 = 0.f;
#pragma unroll
        for (int t = 0; t < 8; t++) {
            s[t][0] = __expf(s[t][0] - mn0); sum0 += s[t][0];
            s[t][1] = __expf(s[t][1] - mn0); sum0 += s[t][1];
            s[t][2] = __expf(s[t][2] - mn1); sum1 += s[t][2];
            s[t][3] = __expf(s[t][3] - mn1); sum1 += s[t][3];
        }
        sum0 += __shfl_xor_sync(0xffffffffu, sum0, 1);
        sum0 += __shfl_xor_sync(0xffffffffu, sum0, 2);
        sum1 += __shfl_xor_sync(0xffffffffu, sum1, 1);
        sum1 += __shfl_xor_sync(0xffffffffu, sum1, 2);
        lr0 = lr0 * a0 + sum0;
        lr1 = lr1 * a1 + sum1;
#pragma unroll
        for (int dt = 0; dt < 8; dt++) {
            O[dt][0] *= a0; O[dt][1] *= a0;
            O[dt][2] *= a1; O[dt][3] *= a1;
        }

        // ---- O += P V (P packed to fp16 A fragments in registers) ----
#pragma unroll
        for (int js = 0; js < 4; js++) {
            uint32_t ap[4];
            ap[0] = pack2h(s[2 * js][0],     s[2 * js][1]);
            ap[1] = pack2h(s[2 * js][2],     s[2 * js][3]);
            ap[2] = pack2h(s[2 * js + 1][0], s[2 * js + 1][1]);
            ap[3] = pack2h(s[2 * js + 1][2], s[2 * js + 1][3]);
#pragma unroll
            for (int dp = 0; dp < 4; dp++) {
                uint32_t vf[4];
                const uint32_t off = SWZ((uint32_t)(
                    (js * 16 + (qq & 1) * 8 + l8) * 128 + dp * 32 + (qq >> 1) * 16));
                ldsm_x4_t(vf, kb + 8192u + off);
                mma_f16(O[2 * dp + 0], ap, vf[0], vf[1]);
                mma_f16(O[2 * dp + 1], ap, vf[2], vf[3]);
            }
        }
        buf = (buf + 1 >= 3) ? 0 : buf + 1;
    }
#undef ISSUE_KV

    // ---- epilogue: normalize, fp16, token-major out ----
    const float inv0 = 1.f / lr0, inv1 = 1.f / lr1;
    const int t0 = qi * 128 + m0 + g;
    const size_t base0 = ((size_t)(b * 1024 + t0)) * 1024 + h * 64;
    const size_t base1 = base0 + 8 * 1024;
#pragma unroll
    for (int dt = 0; dt < 8; dt++) {
        const int d0 = dt * 8 + tg * 2;
        *(uint32_t*)(ao + base0 + d0) = pack2h(O[dt][0] * inv0, O[dt][1] * inv0);
        *(uint32_t*)(ao + base1 + d0) = pack2h(O[dt][2] * inv1, O[dt][3] * inv1);
    }
}

// ---------------------------------------------------------------------------
extern "C" void kernel_launch(void* const* d_in, const int* in_sizes, int n_in,
                              void* d_out, int out_size)
{
    (void)in_sizes; (void)n_in; (void)out_size;
    const float* x      = (const float*)d_in[0];
    const float* w_qkv  = (const float*)d_in[1];
    const float* biases = (const float*)d_in[2];
    const float* w_out  = (const float*)d_in[4];
    const float* b_out  = (const float*)d_in[5];
    float* out = (float*)d_out;

    __half *q, *k, *v, *x16, *w1, *w2, *ao;
    cudaGetSymbolAddress((void**)&q, g_q);
    cudaGetSymbolAddress((void**)&k, g_k);
    cudaGetSymbolAddress((void**)&v, g_v);
    cudaGetSymbolAddress((void**)&x16, g_x16);
    cudaGetSymbolAddress((void**)&w1, g_w1);
    cudaGetSymbolAddress((void**)&w2, g_w2);
    cudaGetSymbolAddress((void**)&ao, g_ao);

    cudaFuncSetAttribute(gemm_hmma<0>, cudaFuncAttributeMaxDynamicSharedMemorySize, GEMM_SMEM);
    cudaFuncSetAttribute(gemm_hmma<1>, cudaFuncAttributeMaxDynamicSharedMemorySize, GEMM_SMEM);
    cudaFuncSetAttribute(attn_tc, cudaFuncAttributeMaxDynamicSharedMemorySize, AT_SMEM);

    // 1) fp16 converts of inputs
    to_fp16<<<8192, 256>>>(x, x16, 8192 * 1024 / 4);
    to_fp16<<<3072, 256>>>(w_qkv, w1, 3072 * 1024 / 4);
    to_fp16<<<1024, 256>>>(w_out, w2, 1024 * 1024 / 4);

    // 2) QKV projection -> head-major fp16 q/k/v (q pre-scaled)
    {
        dim3 grid(3072 / 256, 8192 / 128);
        gemm_hmma<0><<<grid, 256, GEMM_SMEM>>>(x16, w1, nullptr, nullptr, 0, q, k, v);
    }

    // 3) fp16 tensor-core flash attention -> ao
    {
        dim3 grid(8, 128);
        attn_tc<<<grid, 256, AT_SMEM>>>(q, k, v, biases, ao);
    }

    // 4) Output projection + bias -> fp32 out
    {
        dim3 grid(1024 / 256, 8192 / 128);
        gemm_hmma<1><<<grid, 256, GEMM_SMEM>>>(ao, w2, b_out, out, 1024,
                                               nullptr, nullptr, nullptr);
    }
}